// round 8
// baseline (speedup 1.0000x reference)
#include <cuda_runtime.h>

typedef unsigned long long u64;

#define HID 10

struct Params {
    const float* W[9];
    const float* b[9];
};

// Dynamic work-stealing counter (reset by reset_kernel before each run).
__device__ unsigned int g_vb_counter;

// Shared weight stash. Hidden weights stored as Whp[l][kk][src][j] where the
// source neuron is k = 5*src + kk; duplicated (w,w) so one LDS.64 feeds a
// packed f32x2 FMA. This layout gives each lane (owning half the neurons)
// fixed base pointers for "own-source" vs "partner-source" rows.
struct __align__(16) SW {
    float2 Whp[7][5][2][HID];  // layers 2..8, duplicated
    float2 bh2[7][HID];        // (b, 0) pre-packed
    float2 W9[HID];            // layer 9 (10 -> 1), duplicated
    float  W1w0[HID];          // layer 1 x-row
    float  W1w1[HID];          // layer 1 t-row
    float  b1[HID];
    float  b9;
};

__device__ __forceinline__ u64 pk2(float lo, float hi) {
    u64 r; asm("mov.b64 %0,{%1,%2};" : "=l"(r) : "f"(lo), "f"(hi)); return r;
}
__device__ __forceinline__ void upk2(u64 v, float& lo, float& hi) {
    asm("mov.b64 {%0,%1},%2;" : "=f"(lo), "=f"(hi) : "l"(v));
}
__device__ __forceinline__ u64 fma2(u64 a, u64 b, u64 c) {
    u64 d; asm("fma.rn.f32x2 %0,%1,%2,%3;" : "=l"(d) : "l"(a), "l"(b), "l"(c)); return d;
}
__device__ __forceinline__ u64 mul2(u64 a, u64 b) {
    u64 d; asm("mul.rn.f32x2 %0,%1,%2;" : "=l"(d) : "l"(a), "l"(b)); return d;
}
__device__ __forceinline__ u64 add2(u64 a, u64 b) {
    u64 d; asm("add.rn.f32x2 %0,%1,%2;" : "=l"(d) : "l"(a), "l"(b)); return d;
}
__device__ __forceinline__ u64 shflx1(u64 v) {
    return __shfl_xor_sync(0xffffffffu, v, 1);
}

// Clamp-free fast tanh: t = 1 - 2/(1 + 2^(2*log2(e)*z)).
// ex2 saturates to +inf / 0 at the extremes, rcp maps those to 0 / 1,
// giving exactly +-1 — NaN-free for all finite z.
__device__ __forceinline__ float tanh_fast(float z) {
    float p = z * 2.8853900817779268f;   // 2 * log2(e)
    float e;
    asm("ex2.approx.f32 %0, %1;" : "=f"(e) : "f"(p));
    float r;
    asm("rcp.approx.f32 %0, %1;" : "=f"(r) : "f"(e + 1.0f));
    return fmaf(-2.0f, r, 1.0f);
}

__device__ __forceinline__ void load_weights(SW& s, const Params& p) {
    int t = threadIdx.x;
    // Whp[l][kk][src][j] = W[l+1][(5*src+kk)*10 + j], duplicated
    for (int l = 0; l < 7; l++)
        for (int i = t; i < HID * HID; i += blockDim.x) {
            int k = i / HID, j = i % HID;
            float w = p.W[l + 1][i];
            s.Whp[l][k % 5][k / 5][j] = make_float2(w, w);
        }
    for (int l = 0; l < 7; l++)
        for (int i = t; i < HID; i += blockDim.x)
            s.bh2[l][i] = make_float2(p.b[l + 1][i], 0.0f);
    for (int i = t; i < HID; i += blockDim.x) {
        s.W1w0[i] = p.W[0][i];            // row 0 (x)
        s.W1w1[i] = p.W[0][HID + i];      // row 1 (t)
        s.b1[i]   = p.b[0][i];
        float w9  = p.W[8][i];
        s.W9[i]   = make_float2(w9, w9);
    }
    if (t == 0) s.b9 = p.b[8][0];
}

__global__ void reset_kernel() {
    g_vb_counter = 0;
}

// ---------------------------------------------------------------------------
// Persistent fused kernel, dynamic work-stealing over virtual blocks.
//   vb in [0, nfBlocks): jet path — TWO lanes per point (lane pair via
//     shfl.xor 1), each lane owns 5 of the 10 hidden neurons. 64 points/vb.
//     2nd-order forward-mode AD: P = (u, u_xx-jet), Q = (u_x, u_t).
//   vb in [nfBlocks, totalVB): forward-only path, 1 point/thread, 128/vb.
// ---------------------------------------------------------------------------
__global__ void __launch_bounds__(128, 7)
fused_kernel(const float* __restrict__ Xf,
             const float* __restrict__ p0, const float* __restrict__ p1,
             const float* __restrict__ p2,
             Params p, float* __restrict__ out,
             int nf, int n0, int nb)
{
    __shared__ SW s;
    __shared__ int s_vb;
    load_weights(s, p);
    __syncthreads();

    const int nfBlocks = (nf + 63) >> 6;            // 64 jet points per vb
    const int total    = n0 + 2 * nb;
    const int totalVB  = nfBlocks + ((total + 127) >> 7);

    const int half  = threadIdx.x & 1;
    const int jbase = 5 * half;

    for (;;) {
        if (threadIdx.x == 0)
            s_vb = (int)atomicAdd(&g_vb_counter, 1u);
        __syncthreads();
        int vb = s_vb;
        if (vb >= totalVB) break;
        __syncthreads();   // protect s_vb before next overwrite

        if (vb >= nfBlocks) {
            // ---------------- forward-only path ----------------
            int i = (vb - nfBlocks) * 128 + threadIdx.x;
            if (i >= total) continue;

            const float* src;
            int loc, off;
            if (i < n0)           { src = p0; loc = i;           off = nf; }
            else if (i < n0 + nb) { src = p1; loc = i - n0;      off = nf + n0; }
            else                  { src = p2; loc = i - n0 - nb; off = nf + n0 + nb; }

            float x  = src[2 * loc + 0];
            float tt = src[2 * loc + 1];

            float h[HID];
            #pragma unroll
            for (int j = 0; j < HID; j++)
                h[j] = tanh_fast(fmaf(x, s.W1w0[j], fmaf(tt, s.W1w1[j], s.b1[j])));

            #pragma unroll 1
            for (int l = 0; l < 7; l++) {
                float z[HID];
                #pragma unroll
                for (int j = 0; j < HID; j++) z[j] = s.bh2[l][j].x;
                #pragma unroll
                for (int k = 0; k < HID; k++) {
                    float hk = h[k];
                    #pragma unroll
                    for (int j = 0; j < HID; j++)
                        z[j] = fmaf(hk, s.Whp[l][k % 5][k / 5][j].x, z[j]);
                }
                #pragma unroll
                for (int j = 0; j < HID; j++) h[j] = tanh_fast(z[j]);
            }

            float u = s.b9;
            #pragma unroll
            for (int k = 0; k < HID; k++) u = fmaf(h[k], s.W9[k].x, u);

            out[off + loc] = u;
            continue;
        }

        // ---------------- jet path: 2 lanes per point ----------------
        int i = vb * 64 + (threadIdx.x >> 1);        // point index
        int c = min(i, nf - 1);

        float2 xy = reinterpret_cast<const float2*>(Xf)[c];

        u64 P[5], Q[5];   // this lane's 5 neurons: j = jbase + jj

        // Layer 1: input (x,t); a_x=(1,0), a_t=(0,1), a_xx=0.
        #pragma unroll
        for (int jj = 0; jj < 5; jj++) {
            int j = jbase + jj;
            float w0 = s.W1w0[j];
            float w1 = s.W1w1[j];
            float z  = fmaf(xy.x, w0, fmaf(xy.y, w1, s.b1[j]));
            float t  = tanh_fast(z);
            float sv = fmaf(-t, t, 1.0f);
            P[jj] = pk2(t, -2.0f * t * sv * w0 * w0);   // zxx = 0, zx = w0
            Q[jj] = pk2(sv * w0, sv * w1);
        }

        // Hidden layers 2..8
        #pragma unroll 1
        for (int l = 0; l < 7; l++) {
            u64 zP[5], zQ[5];
            #pragma unroll
            for (int jj = 0; jj < 5; jj++) {
                zP[jj] = *reinterpret_cast<const u64*>(&s.bh2[l][jbase + jj]);
                zQ[jj] = 0ull;
            }
            #pragma unroll
            for (int kk = 0; kk < 5; kk++) {
                u64 Pm = P[kk], Qm = Q[kk];          // source k = jbase + kk
                u64 Po = shflx1(Pm);                 // partner: k = 5-jbase+... (other half)
                u64 Qo = shflx1(Qm);
                const u64* wm =
                    reinterpret_cast<const u64*>(&s.Whp[l][kk][half][jbase]);
                const u64* wo =
                    reinterpret_cast<const u64*>(&s.Whp[l][kk][half ^ 1][jbase]);
                #pragma unroll
                for (int jj = 0; jj < 5; jj++) {
                    u64 w1v = wm[jj];
                    u64 w2v = wo[jj];
                    zP[jj] = fma2(Pm, w1v, zP[jj]);
                    zQ[jj] = fma2(Qm, w1v, zQ[jj]);
                    zP[jj] = fma2(Po, w2v, zP[jj]);
                    zQ[jj] = fma2(Qo, w2v, zQ[jj]);
                }
            }
            #pragma unroll
            for (int jj = 0; jj < 5; jj++) {
                float z, zxx;  upk2(zP[jj], z, zxx);
                float zx, zt;  upk2(zQ[jj], zx, zt);
                (void)zt;
                float t  = tanh_fast(z);
                float sv = fmaf(-t, t, 1.0f);
                P[jj] = pk2(t, fmaf(sv, zxx, -2.0f * t * sv * zx * zx));
                Q[jj] = mul2(zQ[jj], pk2(sv, sv));
            }
        }

        // Output layer (10 -> 1): partial over own 5 neurons, pair-reduce.
        u64 aP = half ? 0ull : pk2(s.b9, 0.0f);
        u64 aQ = 0ull;
        #pragma unroll
        for (int kk = 0; kk < 5; kk++) {
            u64 w = *reinterpret_cast<const u64*>(&s.W9[jbase + kk]);
            aP = fma2(P[kk], w, aP);
            aQ = fma2(Q[kk], w, aQ);
        }
        aP = add2(aP, shflx1(aP));
        aQ = add2(aQ, shflx1(aQ));

        float u, uxx;  upk2(aP, u, uxx);
        float ux, ut;  upk2(aQ, ux, ut);

        const float nu = 0.0031830988618379067f;   // 0.01 / pi
        float f = fmaf(u, ux, fmaf(-nu, uxx, ut)); // u_t + u*u_x - nu*u_xx

        if (half == 0 && i < nf) {
            int offF = nf + n0 + 2 * nb;
            out[i]               = u;
            out[offF + i]        = f;
            out[offF + nf + i]   = ux;
            out[offF + 2*nf + i] = uxx;
        }
    }
}

// ---------------------------------------------------------------------------
// Output layout (reference tuple order, concatenated):
//   [0, nf) u_pred_f | [nf, +n0) u_pred_0 | [+nb) left | [+nb) right
//   | [+nf) f | [+nf) u_x | [+nf) u_xx
// ---------------------------------------------------------------------------
extern "C" void kernel_launch(void* const* d_in, const int* in_sizes, int n_in,
                              void* d_out, int out_size)
{
    Params p;
    for (int i = 0; i < 9; i++) {
        p.W[i] = (const float*)d_in[4 + 2 * i];
        p.b[i] = (const float*)d_in[5 + 2 * i];
    }
    const float* Xf = (const float*)d_in[0];
    const float* x0 = (const float*)d_in[1];
    const float* xl = (const float*)d_in[2];
    const float* xr = (const float*)d_in[3];

    int nf = in_sizes[0] / 2;
    int n0 = in_sizes[1] / 2;
    int nb = in_sizes[2] / 2;

    float* out = (float*)d_out;

    int nfBlocks  = (nf + 63) / 64;
    int fwdBlocks = (n0 + 2 * nb + 127) / 128;
    int totalVB   = nfBlocks + fwdBlocks;

    // One full wave: 152 SMs (GB300) x 7 blocks/SM.
    int grid = 152 * 7;
    if (grid > totalVB) grid = totalVB;

    reset_kernel<<<1, 1>>>();
    fused_kernel<<<grid, 128>>>(Xf, x0, xl, xr, p, out, nf, n0, nb);
}

// round 9
// speedup vs baseline: 1.1875x; 1.1875x over previous
#include <cuda_runtime.h>

typedef unsigned long long u64;

#define HID 10

struct Params {
    const float* W[9];
    const float* b[9];
};

// Dynamic work-stealing counter (reset by reset_kernel before each run).
__device__ unsigned int g_vb_counter;

// Shared weight stash: weights duplicated into (w,w) float2 so one LDS feeds
// a packed f32x2 FMA; rows 16B-aligned so ulonglong2 reads (LDS.128) fetch
// two duplicated weights per instruction.
struct __align__(16) SW {
    float2 Wh[7][HID][HID];   // layers 2..8 (10 -> 10), duplicated; row = 80B
    float2 bh2[7][HID];       // (b, 0) pre-packed
    float2 W1[2][HID];        // layer 1 (2 -> 10), duplicated
    float2 W9[HID];           // layer 9 (10 -> 1), duplicated
    float  b1[HID];
    float  b9;
};

__device__ __forceinline__ u64 pk2(float lo, float hi) {
    u64 r; asm("mov.b64 %0,{%1,%2};" : "=l"(r) : "f"(lo), "f"(hi)); return r;
}
__device__ __forceinline__ void upk2(u64 v, float& lo, float& hi) {
    asm("mov.b64 {%0,%1},%2;" : "=f"(lo), "=f"(hi) : "l"(v));
}
__device__ __forceinline__ u64 fma2(u64 a, u64 b, u64 c) {
    u64 d; asm("fma.rn.f32x2 %0,%1,%2,%3;" : "=l"(d) : "l"(a), "l"(b), "l"(c)); return d;
}
__device__ __forceinline__ u64 mul2(u64 a, u64 b) {
    u64 d; asm("mul.rn.f32x2 %0,%1,%2;" : "=l"(d) : "l"(a), "l"(b)); return d;
}

// Clamp-free fast tanh: t = 1 - 2/(1 + 2^(2*log2(e)*z)).
// ex2 saturates to +inf / 0 at the extremes, rcp maps those to 0 / 1,
// giving exactly +-1 — NaN-free for all finite z.
__device__ __forceinline__ float tanh_fast(float z) {
    float p = z * 2.8853900817779268f;   // 2 * log2(e)
    float e;
    asm("ex2.approx.f32 %0, %1;" : "=f"(e) : "f"(p));
    float r;
    asm("rcp.approx.f32 %0, %1;" : "=f"(r) : "f"(e + 1.0f));
    return fmaf(-2.0f, r, 1.0f);
}

__device__ __forceinline__ void load_weights(SW& s, const Params& p) {
    int t = threadIdx.x;
    for (int l = 0; l < 7; l++)
        for (int i = t; i < HID * HID; i += blockDim.x) {
            float w = p.W[l + 1][i];
            s.Wh[l][i / HID][i % HID] = make_float2(w, w);
        }
    for (int l = 0; l < 7; l++)
        for (int i = t; i < HID; i += blockDim.x)
            s.bh2[l][i] = make_float2(p.b[l + 1][i], 0.0f);
    for (int i = t; i < 2 * HID; i += blockDim.x) {
        float w = p.W[0][i];
        s.W1[i / HID][i % HID] = make_float2(w, w);
    }
    for (int i = t; i < HID; i += blockDim.x) {
        float w = p.W[8][i];
        s.W9[i] = make_float2(w, w);
    }
    for (int i = t; i < HID; i += blockDim.x) s.b1[i] = p.b[0][i];
    if (t == 0) s.b9 = p.b[8][0];
}

__global__ void reset_kernel() {
    g_vb_counter = 0;
}

// ---------------------------------------------------------------------------
// Persistent fused kernel with dynamic work-stealing over virtual blocks:
//   vb in [0, nfBlocks): jet path, 1 point/thread, LDS.128 weight reads.
//     2nd-order forward-mode AD: P = (u, u_xx-jet), Q = (u_x, u_t).
//   vb in [nfBlocks, totalVB): forward-only path (initial/boundary points).
// Weights are loaded into shared once per block.
// ---------------------------------------------------------------------------
__global__ void __launch_bounds__(128, 5)
fused_kernel(const float* __restrict__ Xf,
             const float* __restrict__ p0, const float* __restrict__ p1,
             const float* __restrict__ p2,
             Params p, float* __restrict__ out,
             int nf, int n0, int nb)
{
    __shared__ SW s;
    __shared__ int s_vb;
    load_weights(s, p);
    __syncthreads();

    const int nfBlocks = (nf + 127) >> 7;
    const int total    = n0 + 2 * nb;
    const int totalVB  = nfBlocks + ((total + 127) >> 7);

    for (;;) {
        if (threadIdx.x == 0)
            s_vb = (int)atomicAdd(&g_vb_counter, 1u);
        __syncthreads();
        int vb = s_vb;
        if (vb >= totalVB) break;
        __syncthreads();   // protect s_vb before next overwrite

        if (vb >= nfBlocks) {
            // ---------------- forward-only path ----------------
            int i = (vb - nfBlocks) * 128 + threadIdx.x;
            if (i >= total) continue;

            const float* src;
            int loc, off;
            if (i < n0)           { src = p0; loc = i;           off = nf; }
            else if (i < n0 + nb) { src = p1; loc = i - n0;      off = nf + n0; }
            else                  { src = p2; loc = i - n0 - nb; off = nf + n0 + nb; }

            float x  = src[2 * loc + 0];
            float tt = src[2 * loc + 1];

            float h[HID];
            #pragma unroll
            for (int j = 0; j < HID; j++)
                h[j] = tanh_fast(fmaf(x, s.W1[0][j].x, fmaf(tt, s.W1[1][j].x, s.b1[j])));

            #pragma unroll 1
            for (int l = 0; l < 7; l++) {
                float z[HID];
                #pragma unroll
                for (int j = 0; j < HID; j++) z[j] = s.bh2[l][j].x;
                #pragma unroll
                for (int k = 0; k < HID; k++) {
                    float hk = h[k];
                    #pragma unroll
                    for (int j = 0; j < HID; j++)
                        z[j] = fmaf(hk, s.Wh[l][k][j].x, z[j]);
                }
                #pragma unroll
                for (int j = 0; j < HID; j++) h[j] = tanh_fast(z[j]);
            }

            float u = s.b9;
            #pragma unroll
            for (int k = 0; k < HID; k++) u = fmaf(h[k], s.W9[k].x, u);

            out[off + loc] = u;
            continue;
        }

        // ---------------- jet path: 1 point per thread ----------------
        int i = vb * 128 + threadIdx.x;
        int c = min(i, nf - 1);

        float2 xy = reinterpret_cast<const float2*>(Xf)[c];

        u64 P[HID], Q[HID];

        // Layer 1: input (x,t); a_x=(1,0), a_t=(0,1), a_xx=0.
        #pragma unroll
        for (int j = 0; j < HID; j++) {
            float w0 = s.W1[0][j].x;
            float w1 = s.W1[1][j].x;
            float z  = fmaf(xy.x, w0, fmaf(xy.y, w1, s.b1[j]));
            float t  = tanh_fast(z);
            float sv = fmaf(-t, t, 1.0f);
            P[j] = pk2(t, -2.0f * t * sv * w0 * w0);   // zxx = 0, zx = w0
            Q[j] = pk2(sv * w0, sv * w1);
        }

        // Hidden layers 2..8 — LDS.128 weight/bias reads (two (w,w) per load)
        #pragma unroll 1
        for (int l = 0; l < 7; l++) {
            u64 zP[HID], zQ[HID];
            const ulonglong2* brow =
                reinterpret_cast<const ulonglong2*>(&s.bh2[l][0]);
            #pragma unroll
            for (int jj = 0; jj < HID / 2; jj++) {
                ulonglong2 bb = brow[jj];     // (b,0),(b,0)
                zP[2*jj]   = bb.x;
                zP[2*jj+1] = bb.y;
                zQ[2*jj]   = 0ull;
                zQ[2*jj+1] = 0ull;
            }
            #pragma unroll
            for (int k = 0; k < HID; k++) {
                u64 Pk = P[k], Qk = Q[k];
                const ulonglong2* wrow =
                    reinterpret_cast<const ulonglong2*>(&s.Wh[l][k][0]);
                #pragma unroll
                for (int jj = 0; jj < HID / 2; jj++) {
                    ulonglong2 w = wrow[jj];  // LDS.128: two duplicated weights
                    zP[2*jj]   = fma2(Pk, w.x, zP[2*jj]);
                    zQ[2*jj]   = fma2(Qk, w.x, zQ[2*jj]);
                    zP[2*jj+1] = fma2(Pk, w.y, zP[2*jj+1]);
                    zQ[2*jj+1] = fma2(Qk, w.y, zQ[2*jj+1]);
                }
            }
            #pragma unroll
            for (int j = 0; j < HID; j++) {
                float z, zxx;  upk2(zP[j], z, zxx);
                float zx, zt;  upk2(zQ[j], zx, zt);
                (void)zt;
                float t  = tanh_fast(z);
                float sv = fmaf(-t, t, 1.0f);
                P[j] = pk2(t, fmaf(sv, zxx, -2.0f * t * sv * zx * zx));
                Q[j] = mul2(zQ[j], pk2(sv, sv));
            }
        }

        // Output layer (10 -> 1), linear.
        u64 aP = pk2(s.b9, 0.0f);
        u64 aQ = 0ull;
        #pragma unroll
        for (int kk = 0; kk < HID / 2; kk++) {
            ulonglong2 w =
                reinterpret_cast<const ulonglong2*>(&s.W9[0])[kk];
            aP = fma2(P[2*kk],   w.x, aP);
            aQ = fma2(Q[2*kk],   w.x, aQ);
            aP = fma2(P[2*kk+1], w.y, aP);
            aQ = fma2(Q[2*kk+1], w.y, aQ);
        }
        float u, uxx;  upk2(aP, u, uxx);
        float ux, ut;  upk2(aQ, ux, ut);

        const float nu = 0.0031830988618379067f;   // 0.01 / pi
        float f = fmaf(u, ux, fmaf(-nu, uxx, ut)); // u_t + u*u_x - nu*u_xx

        if (i < nf) {
            int offF = nf + n0 + 2 * nb;
            out[i]               = u;
            out[offF + i]        = f;
            out[offF + nf + i]   = ux;
            out[offF + 2*nf + i] = uxx;
        }
    }
}

// ---------------------------------------------------------------------------
// Output layout (reference tuple order, concatenated):
//   [0, nf) u_pred_f | [nf, +n0) u_pred_0 | [+nb) left | [+nb) right
//   | [+nf) f | [+nf) u_x | [+nf) u_xx
// ---------------------------------------------------------------------------
extern "C" void kernel_launch(void* const* d_in, const int* in_sizes, int n_in,
                              void* d_out, int out_size)
{
    Params p;
    for (int i = 0; i < 9; i++) {
        p.W[i] = (const float*)d_in[4 + 2 * i];
        p.b[i] = (const float*)d_in[5 + 2 * i];
    }
    const float* Xf = (const float*)d_in[0];
    const float* x0 = (const float*)d_in[1];
    const float* xl = (const float*)d_in[2];
    const float* xr = (const float*)d_in[3];

    int nf = in_sizes[0] / 2;
    int n0 = in_sizes[1] / 2;
    int nb = in_sizes[2] / 2;

    float* out = (float*)d_out;

    int nfBlocks  = (nf + 127) / 128;
    int fwdBlocks = (n0 + 2 * nb + 127) / 128;
    int totalVB   = nfBlocks + fwdBlocks;

    // One full wave: 152 SMs (GB300) x 5 blocks/SM.
    int grid = 152 * 5;
    if (grid > totalVB) grid = totalVB;

    reset_kernel<<<1, 1>>>();
    fused_kernel<<<grid, 128>>>(Xf, x0, xl, xr, p, out, nf, n0, nb);
}